// round 7
// baseline (speedup 1.0000x reference)
#include <cuda_runtime.h>
#include <math_constants.h>

#define B_      8
#define H_      32
#define DK_     128
#define DM_     4096
#define MAXLEN_ 4096
#define SPLIT_  4
#define KQ_     3          // k-split for qkv projections (ragged over 16 chunks)
#define KO_     2          // k-split for output projection
#define CHUNKS_ 16         // 4096 cols / 256 cols-per-chunk

// Scratch (no allocation allowed in kernel_launch)
__device__ float g_qp[KQ_][B_ * DM_];
__device__ float g_kp[KQ_][B_ * DM_];
__device__ float g_vp[KQ_][B_ * DM_];
__device__ float g_op[KO_][B_ * DM_];
__device__ float g_attn[B_ * DM_];
__device__ float g_pm[B_ * H_ * SPLIT_];
__device__ float g_pl[B_ * H_ * SPLIT_];
__device__ float g_pa[B_ * H_ * SPLIT_ * DK_];

__device__ __forceinline__ float dot4(float4 a, float4 b) {
    return a.x * b.x + a.y * b.y + a.z * b.z + a.w * b.w;
}
__device__ __forceinline__ float4 add4(float4 a, float4 b) {
    return make_float4(a.x + b.x, a.y + b.y, a.z + b.z, a.w + b.w);
}

// ---- packed f32x2 helpers (sm_103a FFMA2 via PTX) -------------------------
__device__ __forceinline__ unsigned long long pack2(float lo, float hi) {
    unsigned long long r;
    asm("mov.b64 %0, {%1, %2};" : "=l"(r) : "f"(lo), "f"(hi));
    return r;
}
__device__ __forceinline__ void fma2(unsigned long long& acc,
                                     unsigned long long a,
                                     unsigned long long b) {
    asm("fma.rn.f32x2 %0, %1, %2, %0;" : "+l"(acc) : "l"(a), "l"(b));
}
__device__ __forceinline__ float2 unpack2(unsigned long long p) {
    float2 r;
    asm("mov.b64 {%0, %1}, %2;" : "=f"(r.x), "=f"(r.y) : "l"(p));
    return r;
}

// ---------------------------------------------------------------------------
// Split-K GEMV partial: yp[b][j] = sum_{i in slice} x[b][i] * W[j][i]
// 8 warps x 4 rows = 32 rows/block. x slice staged in smem. Inner product via
// packed fma.rn.f32x2, pairing rows (0,1) and (2,3): acc2[p*8+b] holds
// (row 2p, row 2p+1). W pairs packed once per chunk (reused over 8 batches),
// x broadcast pairs on the ALU pipe. Epilogue: butterfly transpose-reduce.
// ---------------------------------------------------------------------------
__device__ __forceinline__ void proj_body(const float4* __restrict__ x4,
                                          const float* __restrict__ W,
                                          float* __restrict__ yp,
                                          int cs, int ce, float4* xs4) {
    const int tid  = threadIdx.x;
    const int warp = tid >> 5;
    const int lane = tid & 31;
    const int row0 = blockIdx.x * 32 + warp * 4;
    const int n4   = (ce - cs) * 64;          // float4 cols in this slice

    // stage x slice: xs4[b*n4 + c] = x4[b*(DM_/4) + cs*64 + c]
    for (int b = 0; b < B_; b++)
        for (int c = tid; c < n4; c += 256)
            xs4[b * n4 + c] = __ldg(x4 + b * (DM_ / 4) + cs * 64 + c);
    __syncthreads();

    unsigned long long acc2[16];              // acc2[p*8+b] = (row 2p, row 2p+1)
    #pragma unroll
    for (int i = 0; i < 16; i++) acc2[i] = 0ull;

    const float4* w0p = (const float4*)(W + (size_t)(row0 + 0) * DM_);
    const float4* w1p = (const float4*)(W + (size_t)(row0 + 1) * DM_);
    const float4* w2p = (const float4*)(W + (size_t)(row0 + 2) * DM_);
    const float4* w3p = (const float4*)(W + (size_t)(row0 + 3) * DM_);

    #pragma unroll 2
    for (int it = cs; it < ce; ++it) {
        const int g0 = it * 64 + lane;        // global float4 col
        const int g1 = g0 + 32;
        const int c0 = (it - cs) * 64 + lane; // local float4 col in smem
        const int c1 = c0 + 32;

        const float4 wa0 = __ldcs(w0p + g0), wb0 = __ldcs(w0p + g1);
        const float4 wa1 = __ldcs(w1p + g0), wb1 = __ldcs(w1p + g1);
        const float4 wa2 = __ldcs(w2p + g0), wb2 = __ldcs(w2p + g1);
        const float4 wa3 = __ldcs(w3p + g0), wb3 = __ldcs(w3p + g1);

        // pack W row-pairs (reused across all 8 batches)
        const unsigned long long pa0x = pack2(wa0.x, wa1.x), pa0y = pack2(wa0.y, wa1.y),
                                 pa0z = pack2(wa0.z, wa1.z), pa0w = pack2(wa0.w, wa1.w);
        const unsigned long long pa1x = pack2(wa2.x, wa3.x), pa1y = pack2(wa2.y, wa3.y),
                                 pa1z = pack2(wa2.z, wa3.z), pa1w = pack2(wa2.w, wa3.w);
        const unsigned long long pb0x = pack2(wb0.x, wb1.x), pb0y = pack2(wb0.y, wb1.y),
                                 pb0z = pack2(wb0.z, wb1.z), pb0w = pack2(wb0.w, wb1.w);
        const unsigned long long pb1x = pack2(wb2.x, wb3.x), pb1y = pack2(wb2.y, wb3.y),
                                 pb1z = pack2(wb2.z, wb3.z), pb1w = pack2(wb2.w, wb3.w);

        #pragma unroll
        for (int b = 0; b < B_; b++) {
            const float4 xa = xs4[b * n4 + c0];
            const unsigned long long xax = pack2(xa.x, xa.x), xay = pack2(xa.y, xa.y),
                                     xaz = pack2(xa.z, xa.z), xaw = pack2(xa.w, xa.w);
            fma2(acc2[0 * 8 + b], pa0x, xax); fma2(acc2[1 * 8 + b], pa1x, xax);
            fma2(acc2[0 * 8 + b], pa0y, xay); fma2(acc2[1 * 8 + b], pa1y, xay);
            fma2(acc2[0 * 8 + b], pa0z, xaz); fma2(acc2[1 * 8 + b], pa1z, xaz);
            fma2(acc2[0 * 8 + b], pa0w, xaw); fma2(acc2[1 * 8 + b], pa1w, xaw);
            const float4 xb = xs4[b * n4 + c1];
            const unsigned long long xbx = pack2(xb.x, xb.x), xby = pack2(xb.y, xb.y),
                                     xbz = pack2(xb.z, xb.z), xbw = pack2(xb.w, xb.w);
            fma2(acc2[0 * 8 + b], pb0x, xbx); fma2(acc2[1 * 8 + b], pb1x, xbx);
            fma2(acc2[0 * 8 + b], pb0y, xby); fma2(acc2[1 * 8 + b], pb1y, xby);
            fma2(acc2[0 * 8 + b], pb0z, xbz); fma2(acc2[1 * 8 + b], pb1z, xbz);
            fma2(acc2[0 * 8 + b], pb0w, xbw); fma2(acc2[1 * 8 + b], pb1w, xbw);
        }
    }

    // unfold: acc[r*8+b], r = 2p + (lo/hi)
    float acc[32];
    #pragma unroll
    for (int p = 0; p < 2; p++)
        #pragma unroll
        for (int b = 0; b < B_; b++) {
            const float2 v = unpack2(acc2[p * 8 + b]);
            acc[16 * p + b]     = v.x;
            acc[16 * p + 8 + b] = v.y;
        }

    // Butterfly transpose-reduce: lane L ends holding full sum of acc[L].
    #pragma unroll
    for (int o = 16; o >= 1; o >>= 1) {
        const bool up = (lane & o) != 0;
        #pragma unroll
        for (int k = 0; k < o; k++) {
            const float keep = up ? acc[k + o] : acc[k];
            const float send = up ? acc[k]     : acc[k + o];
            acc[k] = keep + __shfl_xor_sync(0xffffffffu, send, o);
        }
    }
    const int r = lane >> 3;
    const int b = lane & 7;
    yp[b * DM_ + row0 + r] = acc[0];
}

__global__ void __launch_bounds__(256, 2)
proj_qkv_kernel(const float* __restrict__ q_in, const float* __restrict__ k_in,
                const float* __restrict__ v_in,
                const float* __restrict__ Wq, const float* __restrict__ Wk,
                const float* __restrict__ Wv) {
    extern __shared__ float4 xs4[];
    const int ks = blockIdx.y;
    const int cs = (CHUNKS_ * ks) / KQ_;
    const int ce = (CHUNKS_ * (ks + 1)) / KQ_;
    const float* x; const float* W; float* y;
    if (blockIdx.z == 0)      { x = q_in; W = Wq; y = g_qp[ks]; }
    else if (blockIdx.z == 1) { x = k_in; W = Wk; y = g_kp[ks]; }
    else                      { x = v_in; W = Wv; y = g_vp[ks]; }
    proj_body((const float4*)x, W, y, cs, ce, xs4);
}

__global__ void __launch_bounds__(256, 2)
proj_out_kernel(const float* __restrict__ Wo) {
    extern __shared__ float4 xs4[];
    const int ks = blockIdx.y;
    const int cs = (CHUNKS_ * ks) / KO_;
    const int ce = (CHUNKS_ * (ks + 1)) / KO_;
    proj_body((const float4*)g_attn, Wo, g_op[ks], cs, ce, xs4);
}

__global__ void __launch_bounds__(256)
final_add_kernel(const float* __restrict__ bo, float* __restrict__ out) {
    const int i = blockIdx.x * 256 + threadIdx.x;
    out[i] = g_op[0][i] + g_op[1][i] + bo[i & (DM_ - 1)];
}

// ---------------------------------------------------------------------------
// Attention, split-K over keys (at HBM roofline — structure unchanged).
// ---------------------------------------------------------------------------
__global__ void __launch_bounds__(256)
attn_kernel(const float* __restrict__ kc, const float* __restrict__ vc,
            const float* __restrict__ bq, const float* __restrict__ bk,
            const float* __restrict__ bv, const int* __restrict__ cache_len_p) {
    const int bh = blockIdx.x;
    const int b  = bh >> 5;
    const int h  = bh & 31;
    const int s  = blockIdx.y;
    const int L  = cache_len_p[0] + 1;
    const int Lm1 = L - 1;
    const int chunk = (L + SPLIT_ - 1) / SPLIT_;
    const int start = s * chunk;
    const int end   = min(start + chunk, L);

    const int tid  = threadIdx.x;
    const int warp = tid >> 5;
    const int lane = tid & 31;

    const int voff = b * DM_ + h * DK_;
    const float scale = 0.08838834764831843f; // 1/sqrt(128)

    float4 q4   = ((const float4*)(bq + h * DK_))[lane];
    float4 Knew = ((const float4*)(bk + h * DK_))[lane];
    float4 Vnew = ((const float4*)(bv + h * DK_))[lane];
    #pragma unroll
    for (int ks = 0; ks < KQ_; ks++) {
        q4   = add4(q4,   ((const float4*)(g_qp[ks] + voff))[lane]);
        Knew = add4(Knew, ((const float4*)(g_kp[ks] + voff))[lane]);
        Vnew = add4(Vnew, ((const float4*)(g_vp[ks] + voff))[lane]);
    }
    q4.x *= scale; q4.y *= scale; q4.z *= scale; q4.w *= scale;

    const float4* kb = (const float4*)(kc + (((size_t)b * H_ + h) * (size_t)MAXLEN_) * DK_);
    const float4* vb = (const float4*)(vc + (((size_t)b * H_ + h) * (size_t)MAXLEN_) * DK_);

    float m = -CUDART_INF_F;
    float lsum = 0.f;
    float4 a = make_float4(0.f, 0.f, 0.f, 0.f);

    int key = start + warp;
    for (; key + 24 < end; key += 32) {
        const int k1 = key, k2 = key + 8, k3 = key + 16, k4 = key + 24;
        float4 K1 = __ldcs(kb + (size_t)k1 * 32 + lane);
        float4 K2 = __ldcs(kb + (size_t)k2 * 32 + lane);
        float4 K3 = __ldcs(kb + (size_t)k3 * 32 + lane);
        float4 K4 = __ldcs(kb + (size_t)k4 * 32 + lane);
        float4 V1 = __ldcs(vb + (size_t)k1 * 32 + lane);
        float4 V2 = __ldcs(vb + (size_t)k2 * 32 + lane);
        float4 V3 = __ldcs(vb + (size_t)k3 * 32 + lane);
        float4 V4 = __ldcs(vb + (size_t)k4 * 32 + lane);
        if (k1 == Lm1) { K1 = Knew; V1 = Vnew; }
        if (k2 == Lm1) { K2 = Knew; V2 = Vnew; }
        if (k3 == Lm1) { K3 = Knew; V3 = Vnew; }
        if (k4 == Lm1) { K4 = Knew; V4 = Vnew; }

        float s1 = dot4(q4, K1);
        float s2 = dot4(q4, K2);
        float s3 = dot4(q4, K3);
        float s4 = dot4(q4, K4);
        #pragma unroll
        for (int o = 16; o > 0; o >>= 1) {
            s1 += __shfl_xor_sync(0xffffffffu, s1, o);
            s2 += __shfl_xor_sync(0xffffffffu, s2, o);
            s3 += __shfl_xor_sync(0xffffffffu, s3, o);
            s4 += __shfl_xor_sync(0xffffffffu, s4, o);
        }

        const float mn = fmaxf(fmaxf(m, fmaxf(s1, s2)), fmaxf(s3, s4));
        const float corr = __expf(m - mn);
        const float p1 = __expf(s1 - mn);
        const float p2 = __expf(s2 - mn);
        const float p3 = __expf(s3 - mn);
        const float p4 = __expf(s4 - mn);
        lsum = lsum * corr + (p1 + p2) + (p3 + p4);
        a.x = a.x * corr + p1 * V1.x + p2 * V2.x + p3 * V3.x + p4 * V4.x;
        a.y = a.y * corr + p1 * V1.y + p2 * V2.y + p3 * V3.y + p4 * V4.y;
        a.z = a.z * corr + p1 * V1.z + p2 * V2.z + p3 * V3.z + p4 * V4.z;
        a.w = a.w * corr + p1 * V1.w + p2 * V2.w + p3 * V3.w + p4 * V4.w;
        m = mn;
    }
    for (; key < end; key += 8) {
        float4 K1 = __ldcs(kb + (size_t)key * 32 + lane);
        float4 V1 = __ldcs(vb + (size_t)key * 32 + lane);
        if (key == Lm1) { K1 = Knew; V1 = Vnew; }
        float s1 = dot4(q4, K1);
        #pragma unroll
        for (int o = 16; o > 0; o >>= 1) s1 += __shfl_xor_sync(0xffffffffu, s1, o);
        const float mn = fmaxf(m, s1);
        const float corr = __expf(m - mn);
        const float p1 = __expf(s1 - mn);
        lsum = lsum * corr + p1;
        a.x = a.x * corr + p1 * V1.x;
        a.y = a.y * corr + p1 * V1.y;
        a.z = a.z * corr + p1 * V1.z;
        a.w = a.w * corr + p1 * V1.w;
        m = mn;
    }

    __shared__ float  sm_m[8];
    __shared__ float  sm_l[8];
    __shared__ float4 sm_a[8][32];
    if (lane == 0) { sm_m[warp] = m; sm_l[warp] = lsum; }
    sm_a[warp][lane] = a;
    __syncthreads();

    if (tid < 128) {
        float M = sm_m[0];
        #pragma unroll
        for (int w = 1; w < 8; w++) M = fmaxf(M, sm_m[w]);
        float Ls = 0.f, o = 0.f;
        const float* sa = (const float*)sm_a;  // [8][128]
        #pragma unroll
        for (int w = 0; w < 8; w++) {
            const float e = __expf(sm_m[w] - M);
            Ls += e * sm_l[w];
            o  += e * sa[w * 128 + tid];
        }
        const int idx = bh * SPLIT_ + s;
        g_pa[idx * DK_ + tid] = o;
        if (tid == 0) { g_pm[idx] = M; g_pl[idx] = Ls; }
    }
}

__global__ void __launch_bounds__(128)
attn_reduce_kernel() {
    const int bh = blockIdx.x;
    const int d  = threadIdx.x;
    float M = -CUDART_INF_F;
    #pragma unroll
    for (int s = 0; s < SPLIT_; s++) M = fmaxf(M, g_pm[bh * SPLIT_ + s]);
    float Ls = 0.f, o = 0.f;
    #pragma unroll
    for (int s = 0; s < SPLIT_; s++) {
        const int idx = bh * SPLIT_ + s;
        const float e = __expf(g_pm[idx] - M);
        Ls += e * g_pl[idx];
        o  += e * g_pa[idx * DK_ + d];
    }
    g_attn[bh * DK_ + d] = o / Ls;
}

// ---------------------------------------------------------------------------
extern "C" void kernel_launch(void* const* d_in, const int* in_sizes, int n_in,
                              void* d_out, int out_size) {
    const float* query = (const float*)d_in[0];
    const float* keyv  = (const float*)d_in[1];
    const float* value = (const float*)d_in[2];
    const float* kc    = (const float*)d_in[3];
    const float* vc    = (const float*)d_in[4];
    const float* Wq    = (const float*)d_in[5];
    const float* bq    = (const float*)d_in[6];
    const float* Wk    = (const float*)d_in[7];
    const float* bk    = (const float*)d_in[8];
    const float* Wv    = (const float*)d_in[9];
    const float* bv    = (const float*)d_in[10];
    const float* Wo    = (const float*)d_in[11];
    const float* bo    = (const float*)d_in[12];
    const int*   clp   = (const int*)d_in[13];

    // max slice: qkv = 6 chunks (48 KB), out = 8 chunks (64 KB)
    const int smem_qkv = 6 * 64 * B_ * (int)sizeof(float4);
    const int smem_out = 8 * 64 * B_ * (int)sizeof(float4);
    cudaFuncSetAttribute(proj_qkv_kernel, cudaFuncAttributeMaxDynamicSharedMemorySize, smem_qkv);
    cudaFuncSetAttribute(proj_out_kernel, cudaFuncAttributeMaxDynamicSharedMemorySize, smem_out);

    dim3 gqkv(DM_ / 32, KQ_, 3);
    proj_qkv_kernel<<<gqkv, 256, smem_qkv>>>(query, keyv, value, Wq, Wk, Wv);
    dim3 gattn(B_ * H_, SPLIT_);
    attn_kernel<<<gattn, 256>>>(kc, vc, bq, bk, bv, clp);
    attn_reduce_kernel<<<B_ * H_, 128>>>();
    dim3 gout(DM_ / 32, KO_);
    proj_out_kernel<<<gout, 256, smem_out>>>(Wo);
    final_add_kernel<<<B_ * DM_ / 256, 256>>>(bo, (float*)d_out);
}

// round 8
// speedup vs baseline: 1.0692x; 1.0692x over previous
#include <cuda_runtime.h>
#include <math_constants.h>

#define B_      8
#define H_      32
#define DK_     128
#define DM_     4096
#define MAXLEN_ 4096
#define SPLIT_  4
#define KSPLIT_ 2

// Scratch (no allocation allowed in kernel_launch)
__device__ float g_qp[KSPLIT_][B_ * DM_];   // q projection partials
__device__ float g_kp[KSPLIT_][B_ * DM_];
__device__ float g_vp[KSPLIT_][B_ * DM_];
__device__ float g_op[KSPLIT_][B_ * DM_];   // output projection partials
__device__ float g_attn[B_ * DM_];
__device__ float g_pm[B_ * H_ * SPLIT_];
__device__ float g_pl[B_ * H_ * SPLIT_];
__device__ float g_pa[B_ * H_ * SPLIT_ * DK_];

__device__ __forceinline__ float dot4(float4 a, float4 b) {
    return a.x * b.x + a.y * b.y + a.z * b.z + a.w * b.w;
}
__device__ __forceinline__ float4 add4(float4 a, float4 b) {
    return make_float4(a.x + b.x, a.y + b.y, a.z + b.z, a.w + b.w);
}

// ---------------------------------------------------------------------------
// Split-K GEMV partial: yp[b][j] = sum_{i in slice} x[b][i] * W[j][i]
// 8 warps x 4 rows = 32 rows/block; slice = DM/KSPLIT = 2048 cols.
// x slice staged in smem (64KB); W streamed with __ldcs.
// NEW: per-chunk L2 prefetch of the chunk-after-next W tile (one instruction
// per warp: 32 lanes x 1 cache line = the warp's full 4KB chunk). Demand LDGs
// then hit L2 (~250cyc vs 577), fixing the MLP/latency deficit at zero
// register cost.
// Epilogue: butterfly transpose-reduce -> 31 shuffles, 1 STG per lane.
// ---------------------------------------------------------------------------
#define SLICE4_ (DM_ / KSPLIT_ / 4)          // float4 cols per slice (512)
#define NIT_    (DM_ / KSPLIT_ / 256)        // column chunks per slice (8)

__device__ __forceinline__ void proj_body(const float4* __restrict__ x4,
                                          const float* __restrict__ W,
                                          float* __restrict__ yp,
                                          int kslice, float4* xs4) {
    const int tid  = threadIdx.x;
    const int warp = tid >> 5;
    const int lane = tid & 31;
    const int row0 = blockIdx.x * 32 + warp * 4;
    const int cbase = kslice * SLICE4_;      // float4 column base in x

    // stage x slice into smem
    #pragma unroll
    for (int i = tid; i < B_ * SLICE4_; i += 256) {
        const int b = i >> 9;                // /512
        const int c = i & (SLICE4_ - 1);
        xs4[i] = __ldg(x4 + b * (DM_ / 4) + cbase + c);
    }

    // warm L2 with the first two chunks of this warp's W rows while staging
    {
        const float* pf0 = W + (size_t)(row0 + (lane >> 3)) * DM_
                         + (size_t)cbase * 4 + (lane & 7) * 32;
        asm volatile("prefetch.global.L2 [%0];" :: "l"(pf0));
        asm volatile("prefetch.global.L2 [%0];" :: "l"(pf0 + 256));
    }
    __syncthreads();

    float acc[32];                            // acc[r*8+b]
    #pragma unroll
    for (int i = 0; i < 32; i++) acc[i] = 0.f;

    const float4* w0p = (const float4*)(W + (size_t)(row0 + 0) * DM_) + cbase;
    const float4* w1p = (const float4*)(W + (size_t)(row0 + 1) * DM_) + cbase;
    const float4* w2p = (const float4*)(W + (size_t)(row0 + 2) * DM_) + cbase;
    const float4* w3p = (const float4*)(W + (size_t)(row0 + 3) * DM_) + cbase;
    const float*  pfb = W + (size_t)(row0 + (lane >> 3)) * DM_
                      + (size_t)cbase * 4 + (lane & 7) * 32;

    #pragma unroll 2
    for (int it = 0; it < NIT_; ++it) {
        // prefetch chunk it+2 into L2 (one line per lane = warp's whole chunk)
        if (it + 2 < NIT_) {
            asm volatile("prefetch.global.L2 [%0];" :: "l"(pfb + (it + 2) * 256));
        }

        const int c0 = it * 64 + lane;        // local float4 col
        const int c1 = c0 + 32;
        const float4 wa0 = __ldcs(w0p + c0), wb0 = __ldcs(w0p + c1);
        const float4 wa1 = __ldcs(w1p + c0), wb1 = __ldcs(w1p + c1);
        const float4 wa2 = __ldcs(w2p + c0), wb2 = __ldcs(w2p + c1);
        const float4 wa3 = __ldcs(w3p + c0), wb3 = __ldcs(w3p + c1);
        #pragma unroll
        for (int b = 0; b < B_; b++) {
            const float4 xa = xs4[b * SLICE4_ + c0];
            acc[0 * 8 + b] += dot4(wa0, xa);
            acc[1 * 8 + b] += dot4(wa1, xa);
            acc[2 * 8 + b] += dot4(wa2, xa);
            acc[3 * 8 + b] += dot4(wa3, xa);
            const float4 xb = xs4[b * SLICE4_ + c1];
            acc[0 * 8 + b] += dot4(wb0, xb);
            acc[1 * 8 + b] += dot4(wb1, xb);
            acc[2 * 8 + b] += dot4(wb2, xb);
            acc[3 * 8 + b] += dot4(wb3, xb);
        }
    }

    // Butterfly transpose-reduce: lane L ends holding the full cross-lane
    // sum of acc[L]. 31 shuffles total.
    #pragma unroll
    for (int o = 16; o >= 1; o >>= 1) {
        const bool up = (lane & o) != 0;
        #pragma unroll
        for (int k = 0; k < o; k++) {
            const float keep = up ? acc[k + o] : acc[k];
            const float send = up ? acc[k]     : acc[k + o];
            acc[k] = keep + __shfl_xor_sync(0xffffffffu, send, o);
        }
    }
    // acc[0] on lane L = output index L = r*8+b
    const int r = lane >> 3;
    const int b = lane & 7;
    yp[b * DM_ + row0 + r] = acc[0];
}

__global__ void __launch_bounds__(256, 2)
proj_qkv_kernel(const float* __restrict__ q_in, const float* __restrict__ k_in,
                const float* __restrict__ v_in,
                const float* __restrict__ Wq, const float* __restrict__ Wk,
                const float* __restrict__ Wv) {
    extern __shared__ float4 xs4[];
    const int ks = blockIdx.y;
    const float* x; const float* W; float* y;
    if (blockIdx.z == 0)      { x = q_in; W = Wq; y = g_qp[ks]; }
    else if (blockIdx.z == 1) { x = k_in; W = Wk; y = g_kp[ks]; }
    else                      { x = v_in; W = Wv; y = g_vp[ks]; }
    proj_body((const float4*)x, W, y, ks, xs4);
}

__global__ void __launch_bounds__(256, 2)
proj_out_kernel(const float* __restrict__ Wo) {
    extern __shared__ float4 xs4[];
    proj_body((const float4*)g_attn, Wo, g_op[blockIdx.y], blockIdx.y, xs4);
}

__global__ void __launch_bounds__(256)
final_add_kernel(const float* __restrict__ bo, float* __restrict__ out) {
    const int i = blockIdx.x * 256 + threadIdx.x;   // i in [0, B_*DM_)
    out[i] = g_op[0][i] + g_op[1][i] + bo[i & (DM_ - 1)];
}

// ---------------------------------------------------------------------------
// Attention, split-K over keys (at HBM roofline — unchanged).
// ---------------------------------------------------------------------------
__global__ void __launch_bounds__(256)
attn_kernel(const float* __restrict__ kc, const float* __restrict__ vc,
            const float* __restrict__ bq, const float* __restrict__ bk,
            const float* __restrict__ bv, const int* __restrict__ cache_len_p) {
    const int bh = blockIdx.x;
    const int b  = bh >> 5;
    const int h  = bh & 31;
    const int s  = blockIdx.y;
    const int L  = cache_len_p[0] + 1;
    const int Lm1 = L - 1;
    const int chunk = (L + SPLIT_ - 1) / SPLIT_;
    const int start = s * chunk;
    const int end   = min(start + chunk, L);

    const int tid  = threadIdx.x;
    const int warp = tid >> 5;
    const int lane = tid & 31;

    const int voff = b * DM_ + h * DK_;
    const float scale = 0.08838834764831843f; // 1/sqrt(128)

    float4 q4   = ((const float4*)(bq + h * DK_))[lane];
    float4 Knew = ((const float4*)(bk + h * DK_))[lane];
    float4 Vnew = ((const float4*)(bv + h * DK_))[lane];
    #pragma unroll
    for (int ks = 0; ks < KSPLIT_; ks++) {
        q4   = add4(q4,   ((const float4*)(g_qp[ks] + voff))[lane]);
        Knew = add4(Knew, ((const float4*)(g_kp[ks] + voff))[lane]);
        Vnew = add4(Vnew, ((const float4*)(g_vp[ks] + voff))[lane]);
    }
    q4.x *= scale; q4.y *= scale; q4.z *= scale; q4.w *= scale;

    const float4* kb = (const float4*)(kc + (((size_t)b * H_ + h) * (size_t)MAXLEN_) * DK_);
    const float4* vb = (const float4*)(vc + (((size_t)b * H_ + h) * (size_t)MAXLEN_) * DK_);

    float m = -CUDART_INF_F;
    float lsum = 0.f;
    float4 a = make_float4(0.f, 0.f, 0.f, 0.f);

    int key = start + warp;
    for (; key + 24 < end; key += 32) {
        const int k1 = key, k2 = key + 8, k3 = key + 16, k4 = key + 24;
        float4 K1 = __ldcs(kb + (size_t)k1 * 32 + lane);
        float4 K2 = __ldcs(kb + (size_t)k2 * 32 + lane);
        float4 K3 = __ldcs(kb + (size_t)k3 * 32 + lane);
        float4 K4 = __ldcs(kb + (size_t)k4 * 32 + lane);
        float4 V1 = __ldcs(vb + (size_t)k1 * 32 + lane);
        float4 V2 = __ldcs(vb + (size_t)k2 * 32 + lane);
        float4 V3 = __ldcs(vb + (size_t)k3 * 32 + lane);
        float4 V4 = __ldcs(vb + (size_t)k4 * 32 + lane);
        if (k1 == Lm1) { K1 = Knew; V1 = Vnew; }
        if (k2 == Lm1) { K2 = Knew; V2 = Vnew; }
        if (k3 == Lm1) { K3 = Knew; V3 = Vnew; }
        if (k4 == Lm1) { K4 = Knew; V4 = Vnew; }

        float s1 = dot4(q4, K1);
        float s2 = dot4(q4, K2);
        float s3 = dot4(q4, K3);
        float s4 = dot4(q4, K4);
        #pragma unroll
        for (int o = 16; o > 0; o >>= 1) {
            s1 += __shfl_xor_sync(0xffffffffu, s1, o);
            s2 += __shfl_xor_sync(0xffffffffu, s2, o);
            s3 += __shfl_xor_sync(0xffffffffu, s3, o);
            s4 += __shfl_xor_sync(0xffffffffu, s4, o);
        }

        const float mn = fmaxf(fmaxf(m, fmaxf(s1, s2)), fmaxf(s3, s4));
        const float corr = __expf(m - mn);
        const float p1 = __expf(s1 - mn);
        const float p2 = __expf(s2 - mn);
        const float p3 = __expf(s3 - mn);
        const float p4 = __expf(s4 - mn);
        lsum = lsum * corr + (p1 + p2) + (p3 + p4);
        a.x = a.x * corr + p1 * V1.x + p2 * V2.x + p3 * V3.x + p4 * V4.x;
        a.y = a.y * corr + p1 * V1.y + p2 * V2.y + p3 * V3.y + p4 * V4.y;
        a.z = a.z * corr + p1 * V1.z + p2 * V2.z + p3 * V3.z + p4 * V4.z;
        a.w = a.w * corr + p1 * V1.w + p2 * V2.w + p3 * V3.w + p4 * V4.w;
        m = mn;
    }
    for (; key < end; key += 8) {
        float4 K1 = __ldcs(kb + (size_t)key * 32 + lane);
        float4 V1 = __ldcs(vb + (size_t)key * 32 + lane);
        if (key == Lm1) { K1 = Knew; V1 = Vnew; }
        float s1 = dot4(q4, K1);
        #pragma unroll
        for (int o = 16; o > 0; o >>= 1) s1 += __shfl_xor_sync(0xffffffffu, s1, o);
        const float mn = fmaxf(m, s1);
        const float corr = __expf(m - mn);
        const float p1 = __expf(s1 - mn);
        lsum = lsum * corr + p1;
        a.x = a.x * corr + p1 * V1.x;
        a.y = a.y * corr + p1 * V1.y;
        a.z = a.z * corr + p1 * V1.z;
        a.w = a.w * corr + p1 * V1.w;
        m = mn;
    }

    // cross-warp combine -> unnormalized block partial
    __shared__ float  sm_m[8];
    __shared__ float  sm_l[8];
    __shared__ float4 sm_a[8][32];
    if (lane == 0) { sm_m[warp] = m; sm_l[warp] = lsum; }
    sm_a[warp][lane] = a;
    __syncthreads();

    if (tid < 128) {
        float M = sm_m[0];
        #pragma unroll
        for (int w = 1; w < 8; w++) M = fmaxf(M, sm_m[w]);
        float Ls = 0.f, o = 0.f;
        const float* sa = (const float*)sm_a;  // [8][128]
        #pragma unroll
        for (int w = 0; w < 8; w++) {
            const float e = __expf(sm_m[w] - M);
            Ls += e * sm_l[w];
            o  += e * sa[w * 128 + tid];
        }
        const int idx = bh * SPLIT_ + s;
        g_pa[idx * DK_ + tid] = o;
        if (tid == 0) { g_pm[idx] = M; g_pl[idx] = Ls; }
    }
}

__global__ void __launch_bounds__(128)
attn_reduce_kernel() {
    const int bh = blockIdx.x;
    const int d  = threadIdx.x;
    float M = -CUDART_INF_F;
    #pragma unroll
    for (int s = 0; s < SPLIT_; s++) M = fmaxf(M, g_pm[bh * SPLIT_ + s]);
    float Ls = 0.f, o = 0.f;
    #pragma unroll
    for (int s = 0; s < SPLIT_; s++) {
        const int idx = bh * SPLIT_ + s;
        const float e = __expf(g_pm[idx] - M);
        Ls += e * g_pl[idx];
        o  += e * g_pa[idx * DK_ + d];
    }
    g_attn[bh * DK_ + d] = o / Ls;
}

// ---------------------------------------------------------------------------
extern "C" void kernel_launch(void* const* d_in, const int* in_sizes, int n_in,
                              void* d_out, int out_size) {
    const float* query = (const float*)d_in[0];
    const float* keyv  = (const float*)d_in[1];
    const float* value = (const float*)d_in[2];
    const float* kc    = (const float*)d_in[3];
    const float* vc    = (const float*)d_in[4];
    const float* Wq    = (const float*)d_in[5];
    const float* bq    = (const float*)d_in[6];
    const float* Wk    = (const float*)d_in[7];
    const float* bk    = (const float*)d_in[8];
    const float* Wv    = (const float*)d_in[9];
    const float* bv    = (const float*)d_in[10];
    const float* Wo    = (const float*)d_in[11];
    const float* bo    = (const float*)d_in[12];
    const int*   clp   = (const int*)d_in[13];

    const int smem = B_ * SLICE4_ * sizeof(float4);   // 64 KB
    cudaFuncSetAttribute(proj_qkv_kernel, cudaFuncAttributeMaxDynamicSharedMemorySize, smem);
    cudaFuncSetAttribute(proj_out_kernel, cudaFuncAttributeMaxDynamicSharedMemorySize, smem);

    dim3 gqkv(DM_ / 32, KSPLIT_, 3);
    proj_qkv_kernel<<<gqkv, 256, smem>>>(query, keyv, value, Wq, Wk, Wv);
    dim3 gattn(B_ * H_, SPLIT_);
    attn_kernel<<<gattn, 256>>>(kc, vc, bq, bk, bv, clp);
    attn_reduce_kernel<<<B_ * H_, 128>>>();
    dim3 gout(DM_ / 32, KSPLIT_);
    proj_out_kernel<<<gout, 256, smem>>>(Wo);
    final_add_kernel<<<B_ * DM_ / 256, 256>>>(bo, (float*)d_out);
}